// round 15
// baseline (speedup 1.0000x reference)
#include <cuda_runtime.h>

// Shapes (fixed per reference setup_inputs)
#define L_ 12
#define B_ 16
#define H_ 16
#define S_ 577
#define N_ 576      // spatial tokens (S-1)
#define D_ 1024
#define K_ 115      // int(576 * 0.2)

#define ROWS_ 4
#define CHUNKS_ ((K_ + ROWS_ - 1) / ROWS_)   // 29
#define GATHER_PER_B_ (L_ * CHUNKS_)          // 348 gather blocks per batch
#define TOTAL_BLOCKS_ (L_ * B_ * CHUNKS_)     // 5568

#define SLICES_ 18                            // token slices per batch
#define SLICE_TOK_ 32                         // tokens per slice (18*32 = 576)
#define TPT_ 8                                // threads cooperating per token
#define TOPK_BLOCKS_ (B_ * SLICES_)           // 288

#define PAD_ 32                               // 32 ints = 128B -> one line per batch

// Device-global scratch + per-batch sync state (no allocation allowed).
// Each counter/flag lives on its own 128B line. All state returns to 0 by the
// end of every launch -> graph-replay safe (single node, replays serialized).
__device__ int g_topk[B_ * K_];
__device__ __align__(128) int g_done [B_ * PAD_];   // topk slice counters
__device__ __align__(128) int g_flag [B_ * PAD_];   // per-batch ready flags
__device__ __align__(128) int g_gdone[B_ * PAD_];   // gather completion counters

// ---------------------------------------------------------------------------
// Fused kernel, per-batch release.
//   Blocks 0..287: exact top-K rank-count for (batch=bid/18, slice=bid%18);
//     18th arrival per batch raises that batch's flag.
//   All blocks: spin (backoff nanosleep) on the flag of their GATHER batch
//     only, then gather 4 selected K/V rows (float4, streaming).
//   348th gather arrival per batch resets that batch's state for next replay.
// Comparator (v>my)||(v==my && j<t) reproduces jax.lax.top_k ordering
// (desc value, asc index on ties) with unique ranks -> race-free writes.
// ---------------------------------------------------------------------------
__global__ void __launch_bounds__(256) fused_kernel(const float* __restrict__ key,
                                                    const float* __restrict__ val,
                                                    const float* __restrict__ attn,
                                                    float* __restrict__ out) {
    const int bid = blockIdx.x;
    const int tid = threadIdx.x;

    // ---------------- Phase A: top-K (first 288 blocks) ----------------
    if (bid < TOPK_BLOCKS_) {
        __shared__ __align__(16) float sc[N_];
        const int tb = bid / SLICES_;          // topk batch
        const int s  = bid % SLICES_;

        // scores for the whole batch (identical fp32 order in every block
        // -> bitwise-identical scores -> consistent unique ranks)
        const float* bbase = attn + (size_t)tb * H_ * S_ * S_;
        for (int t = tid; t < N_; t += 256) {
            float sum = 0.0f;
            const float* p = bbase + (t + 1);
            #pragma unroll
            for (int h = 0; h < H_; ++h)
                sum += __ldg(p + (size_t)h * (S_ * S_));
            sc[t] = sum;
        }
        __syncthreads();

        // rank 32 tokens of this slice, 8 threads/token, float4 LDS (18 iters)
        const int tok  = s * SLICE_TOK_ + (tid >> 3);
        const int part = tid & (TPT_ - 1);
        const float my = sc[tok];

        const float4* sc4 = reinterpret_cast<const float4*>(sc);
        int rank = 0;
        #pragma unroll
        for (int m = 0; m < (N_ / 4) / TPT_; ++m) {
            const int i = part + m * TPT_;
            const float4 v = sc4[i];
            const int j = 4 * i;
            rank += (v.x > my) || (v.x == my && (j + 0) < tok);
            rank += (v.y > my) || (v.y == my && (j + 1) < tok);
            rank += (v.z > my) || (v.z == my && (j + 2) < tok);
            rank += (v.w > my) || (v.w == my && (j + 3) < tok);
        }
        #pragma unroll
        for (int off = TPT_ / 2; off > 0; off >>= 1)
            rank += __shfl_down_sync(0xffffffffu, rank, off, TPT_);

        if (part == 0 && rank < K_)
            g_topk[tb * K_ + rank] = tok;

        // publish: 18th slice of this batch raises the batch flag
        __syncthreads();
        if (tid == 0) {
            __threadfence();
            if (atomicAdd(&g_done[tb * PAD_], 1) == SLICES_ - 1)
                atomicExch(&g_flag[tb * PAD_], 1);
        }
    }

    // ---------------- Gather mapping ----------------
    const int chunk = bid % CHUNKS_;
    const int b     = (bid / CHUNKS_) % B_;    // gather batch
    const int l     = bid / (CHUNKS_ * B_);
    const int k0    = chunk * ROWS_;

    // ---------------- Wait: this gather batch's flag only ----------------
    if (tid == 0) {
        volatile int* f = &g_flag[b * PAD_];
        int backoff = 32;
        while (*f == 0) {
            __nanosleep(backoff);
            if (backoff < 1024) backoff <<= 1;
        }
    }
    __syncthreads();
    __threadfence();   // order g_topk reads after flag observation

    // ---------------- Phase B: gather 4 K/V rows ----------------
    const size_t src_base = (((size_t)l * B_ + b) * S_) * D_;
    const size_t dst_base = (((size_t)l * B_ + b) * K_) * (size_t)D_;
    const size_t val_out_base = (size_t)L_ * B_ * K_ * D_;

    int src_s[ROWS_];
    #pragma unroll
    for (int r = 0; r < ROWS_; ++r) {
        const int k = k0 + r;
        src_s[r] = (k < K_) ? (g_topk[b * K_ + k] + 1) : -1;
    }

    float4 kr[ROWS_], vr[ROWS_];
    #pragma unroll
    for (int r = 0; r < ROWS_; ++r) {
        if (src_s[r] >= 0) {
            const float* ksrc = key + src_base + (size_t)src_s[r] * D_;
            const float* vsrc = val + src_base + (size_t)src_s[r] * D_;
            kr[r] = __ldcs(reinterpret_cast<const float4*>(ksrc) + tid);
            vr[r] = __ldcs(reinterpret_cast<const float4*>(vsrc) + tid);
        }
    }

    #pragma unroll
    for (int r = 0; r < ROWS_; ++r) {
        const int k = k0 + r;
        if (src_s[r] >= 0) {
            float* kdst = out + dst_base + (size_t)k * D_;
            float* vdst = out + val_out_base + dst_base + (size_t)k * D_;
            __stcs(reinterpret_cast<float4*>(kdst) + tid, kr[r]);
            __stcs(reinterpret_cast<float4*>(vdst) + tid, vr[r]);
        }
    }

    // ---------------- Epilogue: per-batch state reset for next replay -------
    // Readers of g_flag[b] are exactly these 348 blocks; each incremented only
    // after observing flag==1, so the 348th arrival can safely reset.
    __syncthreads();
    if (tid == 0) {
        if (atomicAdd(&g_gdone[b * PAD_], 1) == GATHER_PER_B_ - 1) {
            g_gdone[b * PAD_] = 0;
            g_done [b * PAD_] = 0;
            __threadfence();
            atomicExch(&g_flag[b * PAD_], 0);
        }
    }
}

extern "C" void kernel_launch(void* const* d_in, const int* in_sizes, int n_in,
                              void* d_out, int out_size) {
    const float* key  = (const float*)d_in[0];  // (12,16,577,1024) f32
    const float* val  = (const float*)d_in[1];  // (12,16,577,1024) f32
    const float* attn = (const float*)d_in[2];  // (16,16,577,577)  f32
    float* out = (float*)d_out;                 // keys then values, each (12,16,115,1024)

    fused_kernel<<<TOTAL_BLOCKS_, 256>>>(key, val, attn, out);
}

// round 17
// speedup vs baseline: 1.0324x; 1.0324x over previous
#include <cuda_runtime.h>

// Shapes (fixed per reference setup_inputs)
#define L_ 12
#define B_ 16
#define H_ 16
#define S_ 577
#define N_ 576      // spatial tokens (S-1)
#define D_ 1024
#define K_ 115      // int(576 * 0.2)

#define ROWS_ 4
#define CHUNKS_ ((K_ + ROWS_ - 1) / ROWS_)   // 29
#define GATHER_PER_B_ (L_ * CHUNKS_)          // 348 gather blocks per batch
#define TOTAL_BLOCKS_ (L_ * B_ * CHUNKS_)     // 5568

#define SLICES_ 18                            // token slices per batch
#define SLICE_TOK_ 32                         // tokens per slice (18*32 = 576)
#define TPT_ 8                                // threads cooperating per token
#define TOPK_BLOCKS_ (B_ * SLICES_)           // 288

#define PAD_ 32                               // 32 ints = 128B -> one line per batch

// Device-global scratch + per-batch sync state (no allocation allowed).
// Each counter lives on its own 128B line. All state returns to 0 by the end
// of every launch -> graph-replay safe (single node, replays serialized).
__device__ int g_topk[B_ * K_];
__device__ __align__(128) int g_done [B_ * PAD_];   // topk slice counters (release/acquire)
__device__ __align__(128) int g_gdone[B_ * PAD_];   // gather completion counters

// Acquire load / release reduction — fence-free message passing.
__device__ __forceinline__ int ld_acq(const int* p) {
    int v;
    asm volatile("ld.global.acquire.gpu.b32 %0, [%1];" : "=r"(v) : "l"(p) : "memory");
    return v;
}
__device__ __forceinline__ void red_rel_add(int* p, int v) {
    asm volatile("red.global.add.release.gpu.s32 [%0], %1;" :: "l"(p), "r"(v) : "memory");
}

// ---------------------------------------------------------------------------
// Fused kernel, per-batch release, fence-free sync.
//   Blocks 0..287: exact top-K rank-count for (batch=bid/18, slice=bid%18);
//     each publishes with a release-add on its batch counter.
//   All blocks: acquire-poll their GATHER batch's counter to 18 (release
//     sequence of 18 RMWs -> all g_topk writes visible), then gather 4
//     selected K/V rows (float4, streaming).
//   348th gather arrival per batch resets that batch's state for next replay
//     (provably after every observer of that batch has passed its wait).
// Comparator (v>my)||(v==my && j<t) reproduces jax.lax.top_k ordering
// (desc value, asc index on ties) with unique ranks -> race-free writes.
// Deadlock-free: 48 regs -> 5 blocks/SM -> wave-1 residency ~740 >= 288
// producer blocks (lowest bids), and waiters sleep via __nanosleep.
// ---------------------------------------------------------------------------
__global__ void __launch_bounds__(256) fused_kernel(const float* __restrict__ key,
                                                    const float* __restrict__ val,
                                                    const float* __restrict__ attn,
                                                    float* __restrict__ out) {
    const int bid = blockIdx.x;
    const int tid = threadIdx.x;

    // ---------------- Phase A: top-K (first 288 blocks) ----------------
    if (bid < TOPK_BLOCKS_) {
        __shared__ __align__(16) float sc[N_];
        const int tb = bid / SLICES_;          // topk batch
        const int s  = bid % SLICES_;

        // scores for the whole batch (identical fp32 order in every block
        // -> bitwise-identical scores -> consistent unique ranks)
        const float* bbase = attn + (size_t)tb * H_ * S_ * S_;
        for (int t = tid; t < N_; t += 256) {
            float sum = 0.0f;
            const float* p = bbase + (t + 1);
            #pragma unroll
            for (int h = 0; h < H_; ++h)
                sum += __ldg(p + (size_t)h * (S_ * S_));
            sc[t] = sum;
        }
        __syncthreads();

        // rank 32 tokens of this slice, 8 threads/token, float4 LDS (18 iters)
        const int tok  = s * SLICE_TOK_ + (tid >> 3);
        const int part = tid & (TPT_ - 1);
        const float my = sc[tok];

        const float4* sc4 = reinterpret_cast<const float4*>(sc);
        int rank = 0;
        #pragma unroll
        for (int m = 0; m < (N_ / 4) / TPT_; ++m) {
            const int i = part + m * TPT_;
            const float4 v = sc4[i];
            const int j = 4 * i;
            rank += (v.x > my) || (v.x == my && (j + 0) < tok);
            rank += (v.y > my) || (v.y == my && (j + 1) < tok);
            rank += (v.z > my) || (v.z == my && (j + 2) < tok);
            rank += (v.w > my) || (v.w == my && (j + 3) < tok);
        }
        #pragma unroll
        for (int off = TPT_ / 2; off > 0; off >>= 1)
            rank += __shfl_down_sync(0xffffffffu, rank, off, TPT_);

        if (part == 0 && rank < K_)
            g_topk[tb * K_ + rank] = tok;

        // publish: release-add orders this block's g_topk writes before the
        // increment becomes visible.
        __syncthreads();
        if (tid == 0)
            red_rel_add(&g_done[tb * PAD_], 1);
    }

    // ---------------- Gather mapping ----------------
    const int chunk = bid % CHUNKS_;
    const int b     = (bid / CHUNKS_) % B_;    // gather batch
    const int l     = bid / (CHUNKS_ * B_);
    const int k0    = chunk * ROWS_;

    // ---------------- Wait: acquire-poll this gather batch's counter --------
    if (tid == 0) {
        const int* cnt = &g_done[b * PAD_];
        int backoff = 32;
        while (ld_acq(cnt) < SLICES_) {
            __nanosleep(backoff);
            if (backoff < 128) backoff <<= 1;
        }
    }
    __syncthreads();   // broadcast the acquired visibility to the whole block

    // ---------------- Phase B: gather 4 K/V rows ----------------
    const size_t src_base = (((size_t)l * B_ + b) * S_) * D_;
    const size_t dst_base = (((size_t)l * B_ + b) * K_) * (size_t)D_;
    const size_t val_out_base = (size_t)L_ * B_ * K_ * D_;

    int src_s[ROWS_];
    #pragma unroll
    for (int r = 0; r < ROWS_; ++r) {
        const int k = k0 + r;
        src_s[r] = (k < K_) ? (g_topk[b * K_ + k] + 1) : -1;
    }

    float4 kr[ROWS_], vr[ROWS_];
    #pragma unroll
    for (int r = 0; r < ROWS_; ++r) {
        if (src_s[r] >= 0) {
            const float* ksrc = key + src_base + (size_t)src_s[r] * D_;
            const float* vsrc = val + src_base + (size_t)src_s[r] * D_;
            kr[r] = __ldcs(reinterpret_cast<const float4*>(ksrc) + tid);
            vr[r] = __ldcs(reinterpret_cast<const float4*>(vsrc) + tid);
        }
    }

    #pragma unroll
    for (int r = 0; r < ROWS_; ++r) {
        const int k = k0 + r;
        if (src_s[r] >= 0) {
            float* kdst = out + dst_base + (size_t)k * D_;
            float* vdst = out + val_out_base + dst_base + (size_t)k * D_;
            __stcs(reinterpret_cast<float4*>(kdst) + tid, kr[r]);
            __stcs(reinterpret_cast<float4*>(vdst) + tid, vr[r]);
        }
    }

    // ---------------- Epilogue: per-batch state reset for next replay -------
    // Every reader of g_done[b] has passed its wait before incrementing
    // g_gdone[b] (execution barriers order it), so the 348th arrival can
    // safely zero both counters. Kernel boundary orders this vs next replay.
    __syncthreads();
    if (tid == 0) {
        if (atomicAdd(&g_gdone[b * PAD_], 1) == GATHER_PER_B_ - 1) {
            g_gdone[b * PAD_] = 0;
            g_done [b * PAD_] = 0;
        }
    }
}

extern "C" void kernel_launch(void* const* d_in, const int* in_sizes, int n_in,
                              void* d_out, int out_size) {
    const float* key  = (const float*)d_in[0];  // (12,16,577,1024) f32
    const float* val  = (const float*)d_in[1];  // (12,16,577,1024) f32
    const float* attn = (const float*)d_in[2];  // (16,16,577,577)  f32
    float* out = (float*)d_out;                 // keys then values, each (12,16,115,1024)

    fused_kernel<<<TOTAL_BLOCKS_, 256>>>(key, val, attn, out);
}